// round 17
// baseline (speedup 1.0000x reference)
#include <cuda_runtime.h>
#include <stdint.h>

// Lovasz-Softmax, N=8, C=19, H=W=512.
// R16: hist unchanged from R15 (34.4us, DRAM 63% - near roofline; protect
// the winner). Tail fused: reduce folded INTO scan with the parallelism
// that made R6's reduce fast (1024 thr, bin=tid&255, 4 slice-groups x 37,
// unroll-8 batched L2 loads, smem-atomic merge) - unlike R5's failed
// MLP=1 fusion. Removes one launch + the g_cnt/g_fg round trip.

#define NCLS   19
#define NBINS  256
#define CUTBIN 64                  // drop bg entries with e < 1/4
#define HWSZ   (512 * 512)
#define NPIX   (8 * HWSZ)
#define NBLK   148
#define NTHR_H 1024

#define H_MAG  0x6600u             // fp16 bits of 1536.0 (1.5*2^10)
#define H_MAG2 0x66006600u
#define H_CUT  (H_MAG + CUTBIN)

#define F_L2E  1.4426950408889634f
#define F_MG   12582912.0f         // 1.5 * 2^23
#define F_C4   9.61812910e-3f
#define F_C3   5.55041087e-2f
#define F_C2   2.40226507e-1f
#define F_C1   6.93147181e-1f

typedef unsigned long long u64;

// Per-block partial histograms (packed cnt low16 | fg high16). ~2.9 MB.
__device__ uint32_t g_part[NBLK * NCLS * NBINS];

// ---- packed f32x2 helpers (PTX-only) ----
__device__ __forceinline__ u64 pk(float a, float b) {
    u64 r; asm("mov.b64 %0,{%1,%2};" : "=l"(r) : "f"(a), "f"(b)); return r;
}
__device__ __forceinline__ void upk(u64 v, float& a, float& b) {
    asm("mov.b64 {%0,%1},%2;" : "=f"(a), "=f"(b) : "l"(v));
}
__device__ __forceinline__ u64 f2fma(u64 a, u64 b, u64 c) {
    u64 r; asm("fma.rn.f32x2 %0,%1,%2,%3;" : "=l"(r) : "l"(a), "l"(b), "l"(c));
    return r;
}
__device__ __forceinline__ u64 dup2(float a) { return pk(a, a); }
__device__ __forceinline__ float rcp_fast(float x) {
    float r; asm("rcp.approx.f32 %0,%1;" : "=f"(r) : "f"(x)); return r;
}

// Scalar exp replicating the packed pipeline op-for-op (bit-identical f32).
__device__ __forceinline__ float exp_mirror(float x) {
    float fm = fmaf(x, F_L2E, F_MG);
    float nf = fmaf(fm, -1.0f, F_MG);              // MG - fm = -round(t)
    float f  = fmaf(x, F_L2E, nf);
    float r  = fmaf(F_C4, f, F_C3);
    r = fmaf(r, f, F_C2);
    r = fmaf(r, f, F_C1);
    r = fmaf(r, f, 1.0f);
    return __int_as_float(__float_as_int(r) +
                          __float_as_int(fm) * 8388608);
}

extern __shared__ uint32_t sh[];   // [NCLS*NBINS + 64] (~19.7 KB)

__global__ __launch_bounds__(NTHR_H, 1) void hist_kernel(
    const float* __restrict__ logits, const int* __restrict__ labels,
    float* __restrict__ d_out) {
    int tid = threadIdx.x;
    if (blockIdx.x == 0 && tid == 0) *d_out = 0.0f;
    {
        uint4 z = make_uint4(0, 0, 0, 0);
        uint4* s4 = (uint4*)sh;
        for (int i = tid; i < (NCLS * NBINS + 64) / 4; i += NTHR_H) s4[i] = z;
    }
    __syncthreads();

    const u64 LOG2E = dup2(F_L2E);
    const u64 MG    = dup2(F_MG);
    const u64 NONE  = dup2(-1.0f);
    const u64 C4 = dup2(F_C4);
    const u64 C3 = dup2(F_C3);
    const u64 C2 = dup2(F_C2);
    const u64 C1 = dup2(F_C1);
    const u64 C0 = dup2(1.0f);
    const uint32_t MG16 = H_MAG2;

    const int NELEM  = NPIX / 2;     // float2 pixel pairs
    const int STRIDE = NBLK * NTHR_H;
    for (int q = blockIdx.x * NTHR_H + tid; q < NELEM; q += STRIDE) {
        int p0 = q * 2;
        int n  = p0 >> 18;
        int hw = p0 & (HWSZ - 1);
        const u64* base =
            (const u64*)(logits + (size_t)n * NCLS * HWSZ + hw);

        uint32_t eb[NCLS];         // fp16x2: lo = pixel a, hi = pixel b
        u64 sum2 = pk(0.0f, 0.0f);
#pragma unroll
        for (int c = 0; c < NCLS; c++) {
            u64 xv = base[c * (HWSZ / 2)];         // LDG.64 packed pair
            u64 fm = f2fma(xv, LOG2E, MG);         // t + magic
            u64 nf = f2fma(fm, NONE, MG);          // MG - fm = -round(t)
            u64 f  = f2fma(xv, LOG2E, nf);         // frac in [-0.5, 0.5]
            u64 r  = f2fma(C4, f, C3);
            r = f2fma(r, f, C2);
            r = f2fma(r, f, C1);
            r = f2fma(r, f, C0);
            float fm0, fm1, r0, r1;
            upk(fm, fm0, fm1);
            upk(r, r0, r1);
            // 2^i scale as one IMAD per lane: bits += fm_bits * 2^23
            float e0 = __int_as_float(__float_as_int(r0) +
                                      __float_as_int(fm0) * 8388608);
            float e1 = __int_as_float(__float_as_int(r1) +
                                      __float_as_int(fm1) * 8388608);
            sum2 = f2fma(pk(e0, e1), C0, sum2);    // packed accumulate
            uint32_t w;            // lo = e0 (pixel a)
            asm("cvt.rn.f16x2.f32 %0,%1,%2;" : "=r"(w) : "f"(e1), "f"(e0));
            eb[c] = w;
        }
        float sa, sb;
        upk(sum2, sa, sb);
        float invNa = rcp_fast(sa) * (float)NBINS;
        float invNb = rcp_fast(sb) * (float)NBINS;
        uint32_t inv2;             // lo = pixel a
        asm("cvt.rn.f16x2.f32 %0,%1,%2;" : "=r"(inv2) : "f"(invNb), "f"(invNa));
        int2 lab = *(const int2*)(labels + p0);

#pragma unroll
        for (int c = 0; c < NCLS; c++) {
            uint32_t b2;           // both pixels' bins in one HFMA2
            asm("fma.rn.f16x2 %0,%1,%2,%3;"
                : "=r"(b2) : "r"(eb[c]), "r"(inv2), "r"(MG16));
            uint32_t ra = b2 & 0xFFFFu;
            uint32_t rb = b2 >> 16;
            // unconditional for all classes (spurious label-class count
            // corrected in scan via the mirror identity)
            if (ra >= H_CUT)
                atomicAdd(&sh[c * NBINS + (ra - H_MAG)], 1u);
            if (rb >= H_CUT)
                atomicAdd(&sh[c * NBINS + (rb - H_MAG)], 1u);
        }

        // Label bins via L1-hot gather + bit-exact scalar recompute.
        {
            float xa, xb, dumm;
            u64 va = base[lab.x * (HWSZ / 2)];     // L1 hit (just loaded)
            u64 vb = base[lab.y * (HWSZ / 2)];
            upk(va, xa, dumm);                     // pixel a = lo
            upk(vb, dumm, xb);                     // pixel b = hi
            float ea  = exp_mirror(xa);
            float ebv = exp_mirror(xb);
            uint32_t el2;                          // lo = pixel a
            asm("cvt.rn.f16x2.f32 %0,%1,%2;" : "=r"(el2) : "f"(ebv), "f"(ea));
            uint32_t bl2;
            asm("fma.rn.f16x2 %0,%1,%2,%3;"
                : "=r"(bl2) : "r"(el2), "r"(inv2), "r"(MG16));
            uint32_t bax = bl2 & 0xFFFFu;
            uint32_t bay = bl2 >> 16;
            // fg entries: bin = NBINS - b_label (exact mirror)
            int bfx = min((int)(NBINS - (bax - H_MAG)), NBINS - 1);
            atomicAdd(&sh[lab.x * NBINS + bfx], 0x10001u);
            int bfy = min((int)(NBINS - (bay - H_MAG)), NBINS - 1);
            atomicAdd(&sh[lab.y * NBINS + bfy], 0x10001u);
        }
    }
    __syncthreads();

    uint4* dst = (uint4*)(g_part + (size_t)blockIdx.x * (NCLS * NBINS));
    const uint4* src = (const uint4*)sh;
    for (int i = tid; i < NCLS * NBINS / 4; i += NTHR_H) dst[i] = src[i];
}

// Fused reduce+scan: one block per class, 1024 threads.
// Phase 1 (all 1024): bin = tid&255, slice-group = tid>>8 (4 groups x 37
// slices), unroll-8 batched L2 loads, smem-atomic merge (4-way max).
// Phase 2: mirror-correct + shuffle prefix scan over descending ranks +
// closed-form Lovasz contribution (threads >= 256 carry zeros).
__global__ __launch_bounds__(1024) void scan_kernel(float* __restrict__ d_out) {
    int t = threadIdx.x;
    int c = blockIdx.x;

    __shared__ uint32_t scnt[NBINS], sfg[NBINS];
    __shared__ uint32_t wc[32], wf[32];
    __shared__ float    s_red[32];
    __shared__ float    s_totf;

    if (t < NBINS) { scnt[t] = 0; sfg[t] = 0; }
    __syncthreads();

    // ---- Phase 1: reduce 148 slices (4 threads per bin, 37 slices each) ----
    {
        int bin = t & (NBINS - 1);
        int g   = t >> 8;                      // 0..3
        const uint32_t* p = g_part + c * NBINS + bin;
        uint32_t cs = 0, fs = 0;
#pragma unroll 8
        for (int s = g * 37; s < g * 37 + 37; s++) {
            uint32_t v = __ldg(p + (size_t)s * (NCLS * NBINS));
            cs += v & 0xFFFFu;
            fs += v >> 16;
        }
        if (cs | fs) {
            atomicAdd(&scnt[bin], cs);
            atomicAdd(&sfg[bin], fs);
        }
    }
    __syncthreads();

    // ---- Phase 2: thread t (<256) owns descending rank t -> bin 255-t ----
    uint32_t n = 0, f = 0;
    int b = (NBINS - 1) - t;
    if (t < NBINS) {
        n = scnt[b];
        f = sfg[b];
        // remove spurious label-class bg counts (mirror identity)
        if (b >= CUTBIN) n -= sfg[NBINS - b];
    }

    uint32_t ic = n, fc = f;
    int lane = t & 31, warp = t >> 5;          // 32 warps (24 carry zeros)
#pragma unroll
    for (int d = 1; d < 32; d <<= 1) {
        uint32_t pc = __shfl_up_sync(0xffffffffu, ic, d);
        uint32_t pf = __shfl_up_sync(0xffffffffu, fc, d);
        if (lane >= d) { ic += pc; fc += pf; }
    }
    if (lane == 31) { wc[warp] = ic; wf[warp] = fc; }
    __syncthreads();

    if (t < 32) {
        uint32_t vc = wc[t];
        uint32_t vf = wf[t];
        uint32_t sc2 = vc, sf2 = vf;
#pragma unroll
        for (int d = 1; d < 32; d <<= 1) {
            uint32_t pc = __shfl_up_sync(0xffffffffu, sc2, d);
            uint32_t pf = __shfl_up_sync(0xffffffffu, sf2, d);
            if (t >= d) { sc2 += pc; sf2 += pf; }
        }
        wc[t] = sc2 - vc;                      // exclusive warp offset
        wf[t] = sf2 - vf;
        if (t == 31) s_totf = (float)sf2;      // total fg (warps 8+ add 0)
    }
    __syncthreads();

    float acc = 0.0f;
    if (t < NBINS && n) {
        float gts = s_totf;
        float ccx = (float)(wc[warp] + (ic - n));   // exclusive cum count
        float cfx = (float)(wf[warp] + (fc - f));   // exclusive cum fg
        float un0 = gts + ccx - cfx;
        float Jprev = (un0 > 0.0f) ? 1.0f - (gts - cfx) / un0 : 0.0f;
        float cci = ccx + (float)n;
        float cfi = cfx + (float)f;
        float un  = gts + cci - cfi;                // > 0 since cci > 0
        float J   = 1.0f - (gts - cfi) / un;
        acc = (float)b * (1.0f / (float)NBINS) * (J - Jprev);
    }

#pragma unroll
    for (int d = 16; d > 0; d >>= 1)
        acc += __shfl_down_sync(0xffffffffu, acc, d);
    if (lane == 0) s_red[warp] = acc;
    __syncthreads();
    if (t == 0) {
        float s = 0.0f;
#pragma unroll
        for (int i = 0; i < 8; i++) s += s_red[i];  // warps 8+ contribute 0
        atomicAdd(d_out, s * (1.0f / (float)NCLS));
    }
}

extern "C" void kernel_launch(void* const* d_in, const int* in_sizes, int n_in,
                              void* d_out, int out_size) {
    const float* logits = (const float*)d_in[0];
    const int*   labels = (const int*)d_in[1];
    float* out = (float*)d_out;
    (void)in_sizes; (void)n_in; (void)out_size;

    static bool configured = false;
    if (!configured) {
        cudaFuncSetAttribute(hist_kernel,
                             cudaFuncAttributeMaxDynamicSharedMemorySize,
                             (NCLS * NBINS + 64) * sizeof(uint32_t));
        configured = true;
    }

    hist_kernel<<<NBLK, NTHR_H, (NCLS * NBINS + 64) * sizeof(uint32_t)>>>(
        logits, labels, out);
    scan_kernel<<<NCLS, 1024>>>(out);
}